// round 5
// baseline (speedup 1.0000x reference)
#include <cuda_runtime.h>
#include <cuda.h>
#include <cstdint>

// ---------------- problem constants ----------------
#define N_ROWS  16384
#define D_IN    64
#define D_OUT   32
#define N_PAD   40              // 32 nom | 32:den | 33:alpha | 34..39 zero  (5 n8-tiles)
#define TM      128             // rows per CTA
#define TK      32              // K per pipeline stage (32 fp32 = 128B = SW128 atom)
#define STAGES  8
#define K_ITERS (N_ROWS / TK)   // 512

#define STAGE_A_BYTES (TM * TK * 4)      // 16384
#define STAGE_B_BYTES (TK * N_PAD * 4)   // 5120
#define STAGE_BYTES   (STAGE_A_BYTES + STAGE_B_BYTES)   // 21504 (1024-multiple)
#define SMEM_DYN      (STAGES * STAGE_BYTES + 1024)

#define NWARPS_C 8              // consumer warps (M=16 each)
#define NTHREADS (32 * (NWARPS_C + 1))   // + 1 producer warp

// B operand: Y [N_ROWS][N_PAD] row-major fp32 (tf32-rounded). 2.62 MB scratch.
__device__ float g_Y[N_ROWS * N_PAD];

// ---------------- device helpers ----------------
__device__ __forceinline__ uint32_t smem_u32(const void* p) {
    uint32_t a;
    asm("{ .reg .u64 t; cvta.to.shared.u64 t, %1; cvt.u32.u64 %0, t; }" : "=r"(a) : "l"(p));
    return a;
}
__device__ __forceinline__ float warp_sum(float v) {
    #pragma unroll
    for (int m = 16; m > 0; m >>= 1) v += __shfl_xor_sync(0xffffffffu, v, m);
    return v;
}
__device__ __forceinline__ float artanh_clip(float x) {
    x = fminf(fmaxf(x, -1.0f + 1e-7f), 1.0f - 1e-7f);
    return atanhf(x);
}
__device__ __forceinline__ float tf32_round(float x) {
    uint32_t u;
    asm("cvt.rna.tf32.f32 %0, %1;" : "=r"(u) : "f"(x));
    return __uint_as_float(u);
}
__device__ __forceinline__ uint32_t tf32_bits(float x) {
    uint32_t u;
    asm("cvt.rna.tf32.f32 %0, %1;" : "=r"(u) : "f"(x));
    return u;
}
__device__ __forceinline__ void mbar_init(uint32_t mbar, uint32_t cnt) {
    asm volatile("mbarrier.init.shared.b64 [%0], %1;" :: "r"(mbar), "r"(cnt) : "memory");
}
__device__ __forceinline__ void mbar_expect_tx(uint32_t mbar, uint32_t bytes) {
    asm volatile("mbarrier.arrive.expect_tx.shared.b64 _, [%0], %1;" :: "r"(mbar), "r"(bytes) : "memory");
}
__device__ __forceinline__ void mbar_arrive(uint32_t mbar) {
    asm volatile("mbarrier.arrive.shared.b64 _, [%0];" :: "r"(mbar) : "memory");
}
__device__ __forceinline__ void mbar_wait(uint32_t mbar, uint32_t parity) {
    asm volatile(
        "{\n\t.reg .pred P;\n\t"
        "WL_%=:\n\t"
        "mbarrier.try_wait.parity.shared.b64 P, [%0], %1;\n\t"
        "@!P bra WL_%=;\n\t"
        "}" :: "r"(mbar), "r"(parity) : "memory");
}
__device__ __forceinline__ void tma_load_2d(uint32_t smem_dst, const void* tmap,
                                            int32_t cx, int32_t cy, uint32_t mbar) {
    asm volatile(
        "cp.async.bulk.tensor.2d.shared::cta.global.tile.mbarrier::complete_tx::bytes "
        "[%0], [%1, {%2, %3}], [%4];"
        :: "r"(smem_dst), "l"(tmap), "r"(cx), "r"(cy), "r"(mbar) : "memory");
}
__device__ __forceinline__ float lds32(uint32_t a) {
    float v;
    asm volatile("ld.shared.f32 %0, [%1];" : "=f"(v) : "r"(a));
    return v;
}
__device__ __forceinline__ void mma_tf32(float c[4], uint32_t a0, uint32_t a1, uint32_t a2, uint32_t a3,
                                         uint32_t b0, uint32_t b1) {
    asm volatile(
        "mma.sync.aligned.m16n8k8.row.col.f32.tf32.tf32.f32 "
        "{%0,%1,%2,%3}, {%4,%5,%6,%7}, {%8,%9}, {%0,%1,%2,%3};"
        : "+f"(c[0]), "+f"(c[1]), "+f"(c[2]), "+f"(c[3])
        : "r"(a0), "r"(a1), "r"(a2), "r"(a3), "r"(b0), "r"(b1));
}

// ---------------- kernel 1: build Y = [XW*gamma | gamma-1 | 1 | 0...] ----------------
__global__ __launch_bounds__(1024) void prep_kernel(const float* __restrict__ X,
                                                    const float* __restrict__ W) {
    __shared__ float Ws[D_IN * D_OUT];
    const int tid = threadIdx.x;
    for (int t = tid; t < D_IN * D_OUT; t += 1024) Ws[t] = W[t];
    __syncthreads();

    const int w = tid >> 5, lane = tid & 31;
    const int i = blockIdx.x * 32 + w;

    const float x0 = X[i * D_IN + lane];
    const float x1 = X[i * D_IN + 32 + lane];
    const float xn = fmaxf(sqrtf(warp_sum(x0 * x0 + x1 * x1)), 1e-15f);

    float mx = 0.0f;
    #pragma unroll
    for (int k = 0; k < 32; ++k) mx = fmaf(__shfl_sync(0xffffffffu, x0, k), Ws[k * 32 + lane], mx);
    #pragma unroll
    for (int k = 0; k < 32; ++k) mx = fmaf(__shfl_sync(0xffffffffu, x1, k), Ws[(k + 32) * 32 + lane], mx);

    const float mxn = fmaxf(sqrtf(warp_sum(mx * mx)), 1e-15f);
    const float t   = tanhf((mxn / xn) * artanh_clip(xn));
    const float xw  = t * (mx / mxn);
    const float x2  = warp_sum(xw * xw);
    const float gamma = 2.0f / fmaxf(1.0f - x2, 1e-15f);

    g_Y[i * N_PAD + lane] = tf32_round(xw * gamma);
    if (lane < 8) {
        const float e = (lane == 0) ? (gamma - 1.0f) : ((lane == 1) ? 1.0f : 0.0f);
        g_Y[i * N_PAD + 32 + lane] = tf32_round(e);
    }
}

// ---------------- kernel 2: A @ Y via TMA + mma.sync.tf32 + hyperbolic epilogue ----------------
__global__ __launch_bounds__(NTHREADS, 1) void gemm_kernel(
    const __grid_constant__ CUtensorMap tmA,
    const __grid_constant__ CUtensorMap tmB,
    float* __restrict__ out)
{
    extern __shared__ uint8_t smem_dyn[];
    __shared__ __align__(8) uint64_t full_b[STAGES];
    __shared__ __align__(8) uint64_t empty_b[STAGES];

    const int tid  = threadIdx.x;
    const int wid  = tid >> 5;
    const int lane = tid & 31;

    const uint32_t dyn_base = (smem_u32(smem_dyn) + 1023u) & ~1023u;
    const uint32_t full0  = smem_u32(&full_b[0]);
    const uint32_t empty0 = smem_u32(&empty_b[0]);

    if (tid == 0) {
        for (int s = 0; s < STAGES; ++s) {
            mbar_init(full0 + 8u * s, 1);          // TMA expect_tx completes it
            mbar_init(empty0 + 8u * s, NWARPS_C);  // one arrive per consumer warp
        }
    }
    __syncthreads();

    const int row_base = blockIdx.x * TM;

    if (wid == NWARPS_C) {
        // -------- producer (highest wid -> arbiter priority) --------
        if (lane == 0) {
            uint32_t phase = 1;   // fresh-barrier trick: first empty-wait passes
            for (int it = 0; it < K_ITERS; ++it) {
                const int s = it & (STAGES - 1);
                mbar_wait(empty0 + 8u * s, phase);
                const uint32_t fb = full0 + 8u * s;
                mbar_expect_tx(fb, STAGE_BYTES);
                const uint32_t a_dst = dyn_base + s * STAGE_BYTES;
                const uint32_t b_dst = a_dst + STAGE_A_BYTES;
                const int kbase = it * TK;
                tma_load_2d(a_dst, &tmA, kbase, row_base, fb);  // A box [32 x 128]
                tma_load_2d(b_dst, &tmB, 0, kbase, fb);         // B box [40 x 32]
                if (s == STAGES - 1) phase ^= 1;
            }
        }
        return;
    }

    // -------- consumers: 8 warps, warp owns rows [wid*16, wid*16+16) --------
    float acc[5][4];
    #pragma unroll
    for (int nt = 0; nt < 5; ++nt)
        #pragma unroll
        for (int q = 0; q < 4; ++q) acc[nt][q] = 0.0f;

    const uint32_t row0  = (uint32_t)(wid * 16 + (lane >> 2));  // A frag row (a0/a2)
    const uint32_t aoff0 = row0 * 128u;
    const uint32_t sw    = (row0 & 7u) << 4;                    // SW128 XOR term
    const uint32_t kc4   = (lane & 3u) * 4u;                    // col*4 within k8 group
    const uint32_t boff0 = (lane & 3u) * (N_PAD * 4u) + (lane >> 2) * 4u;  // B (k, n) base

    uint32_t phase = 0;
    for (int it = 0; it < K_ITERS; ++it) {
        const int s = it & (STAGES - 1);
        mbar_wait(full0 + 8u * s, phase);
        const uint32_t Abase = dyn_base + s * STAGE_BYTES;
        const uint32_t Bbase = Abase + STAGE_A_BYTES;

        float af[4][4];
        float bf[4][5][2];
        #pragma unroll
        for (int ks = 0; ks < 4; ++ks) {
            const uint32_t c0 = (uint32_t)ks * 32u + kc4;       // byte col within 128B row
            const uint32_t r0 = Abase + aoff0;
            af[ks][0] = lds32(r0 +          (c0 ^ sw));         // (row,   k)
            af[ks][1] = lds32(r0 + 1024u +  (c0 ^ sw));         // (row+8, k)
            af[ks][2] = lds32(r0 +         ((c0 + 16u) ^ sw));  // (row,   k+4)
            af[ks][3] = lds32(r0 + 1024u + ((c0 + 16u) ^ sw));  // (row+8, k+4)
            const uint32_t bk = Bbase + boff0 + (uint32_t)ks * (8u * N_PAD * 4u);
            #pragma unroll
            for (int nt = 0; nt < 5; ++nt) {
                const uint32_t ba = bk + (uint32_t)nt * 32u;
                bf[ks][nt][0] = lds32(ba);                       // (k,   n)
                bf[ks][nt][1] = lds32(ba + 4u * N_PAD * 4u);     // (k+4, n)
            }
        }
        if (lane == 0) mbar_arrive(empty0 + 8u * s);   // release stage (TMA rewrite >=300cyc away)

        #pragma unroll
        for (int ks = 0; ks < 4; ++ks) {
            const uint32_t a0 = tf32_bits(af[ks][0]);
            const uint32_t a1 = tf32_bits(af[ks][1]);
            const uint32_t a2 = tf32_bits(af[ks][2]);
            const uint32_t a3 = tf32_bits(af[ks][3]);
            #pragma unroll
            for (int nt = 0; nt < 5; ++nt)
                mma_tf32(acc[nt], a0, a1, a2, a3,
                         __float_as_uint(bf[ks][nt][0]), __float_as_uint(bf[ks][nt][1]));
        }
        if (s == STAGES - 1) phase ^= 1;
    }

    // -------- epilogue: hyperbolic chain, per row-half --------
    #pragma unroll
    for (int h = 0; h < 2; ++h) {
        float v[8];
        #pragma unroll
        for (int nt = 0; nt < 4; ++nt) {
            v[2 * nt]     = acc[nt][2 * h];
            v[2 * nt + 1] = acc[nt][2 * h + 1];
        }
        // den at col 32, alpha at col 33 -> lane%4==0 of n-tile 4
        float den   = __shfl_sync(0xffffffffu, acc[4][2 * h],     lane & ~3);
        float alpha = __shfl_sync(0xffffffffu, acc[4][2 * h + 1], lane & ~3);

        const float sgn = (den >= 0.0f) ? 1.0f : -1.0f;
        den = sgn * fmaxf(fabsf(den), 1e-10f);
        const float inv = 1.0f / den;

        float vn2 = 0.0f;
        #pragma unroll
        for (int c = 0; c < 8; ++c) { v[c] *= inv; vn2 += v[c] * v[c]; }
        vn2 += __shfl_xor_sync(0xffffffffu, vn2, 1);
        vn2 += __shfl_xor_sync(0xffffffffu, vn2, 2);

        const float vn = fmaxf(sqrtf(vn2), 1e-15f);
        const float t1 = tanhf(0.5f * artanh_clip(vn));          // ||a_mean||
        const float rn = fmaxf(t1, 1e-15f);
        const float t2 = tanhf(alpha * artanh_clip(rn));
        const float xs = (t1 / vn) * (t2 / rn);                  // x = v * xs
        const float xn = fmaxf(xs * vn, 1e-15f);
        const float k3 = artanh_clip(xn) / xn;
        const float us = xs * k3;                                // >= 0

        float un2 = 0.0f;
        float u[8];
        #pragma unroll
        for (int c = 0; c < 8; ++c) { u[c] = fmaxf(v[c] * us, 0.0f); un2 += u[c] * u[c]; }
        un2 += __shfl_xor_sync(0xffffffffu, un2, 1);
        un2 += __shfl_xor_sync(0xffffffffu, un2, 2);

        const float un = fmaxf(sqrtf(un2), 1e-15f);
        const float k4 = tanhf(un) / un;

        const int row = row_base + wid * 16 + h * 8 + (lane >> 2);
        float* op = out + (size_t)row * D_OUT + 2 * (lane & 3);
        #pragma unroll
        for (int nt = 0; nt < 4; ++nt)
            *reinterpret_cast<float2*>(op + nt * 8) =
                make_float2(u[2 * nt] * k4, u[2 * nt + 1] * k4);
    }
}

// ---------------- host ----------------
typedef CUresult (CUDAAPI *PFN_cuTensorMapEncodeTiled_t)(
    CUtensorMap*, CUtensorMapDataType, cuuint32_t, void*,
    const cuuint64_t*, const cuuint64_t*, const cuuint32_t*, const cuuint32_t*,
    CUtensorMapInterleave, CUtensorMapSwizzle, CUtensorMapL2promotion, CUtensorMapFloatOOBfill);

extern "C" void kernel_launch(void* const* d_in, const int* in_sizes, int n_in,
                              void* d_out, int out_size) {
    const float* X = nullptr; const float* A = nullptr; const float* W = nullptr;
    for (int i = 0; i < n_in; ++i) {
        if (in_sizes[i] == N_ROWS * D_IN)     X = (const float*)d_in[i];
        else if (in_sizes[i] == D_IN * D_OUT) W = (const float*)d_in[i];
        else                                  A = (const float*)d_in[i];   // 16384^2
    }
    float* out = (float*)d_out;

    void* y_ptr = nullptr;
    cudaGetSymbolAddress(&y_ptr, g_Y);

    PFN_cuTensorMapEncodeTiled_t encode = nullptr;
    cudaDriverEntryPointQueryResult qr;
    cudaGetDriverEntryPointByVersion("cuTensorMapEncodeTiled", (void**)&encode,
                                     12000, cudaEnableDefault, &qr);

    CUtensorMap tmA, tmB;
    {   // A: [16384 x 16384] fp32, box [K=32, M=128], SW128 (inner 128B = atom)
        cuuint64_t dims[2]    = {N_ROWS, N_ROWS};
        cuuint64_t strides[1] = {(cuuint64_t)N_ROWS * 4};
        cuuint32_t box[2]     = {TK, TM};
        cuuint32_t estr[2]    = {1, 1};
        encode(&tmA, CU_TENSOR_MAP_DATA_TYPE_FLOAT32, 2, (void*)A,
               dims, strides, box, estr,
               CU_TENSOR_MAP_INTERLEAVE_NONE, CU_TENSOR_MAP_SWIZZLE_128B,
               CU_TENSOR_MAP_L2_PROMOTION_L2_128B, CU_TENSOR_MAP_FLOAT_OOB_FILL_NONE);
    }
    {   // B: Y [16384 x 40] fp32, box [N=40, K=32], no swizzle (contiguous 5120B)
        cuuint64_t dims[2]    = {N_PAD, N_ROWS};
        cuuint64_t strides[1] = {(cuuint64_t)N_PAD * 4};
        cuuint32_t box[2]     = {N_PAD, TK};
        cuuint32_t estr[2]    = {1, 1};
        encode(&tmB, CU_TENSOR_MAP_DATA_TYPE_FLOAT32, 2, y_ptr,
               dims, strides, box, estr,
               CU_TENSOR_MAP_INTERLEAVE_NONE, CU_TENSOR_MAP_SWIZZLE_NONE,
               CU_TENSOR_MAP_L2_PROMOTION_L2_128B, CU_TENSOR_MAP_FLOAT_OOB_FILL_NONE);
    }

    prep_kernel<<<N_ROWS / 32, 1024>>>(X, W);

    cudaFuncSetAttribute(gemm_kernel, cudaFuncAttributeMaxDynamicSharedMemorySize, SMEM_DYN);
    gemm_kernel<<<N_ROWS / TM, NTHREADS, SMEM_DYN>>>(tmA, tmB, out);
}

// round 6
// speedup vs baseline: 1.4729x; 1.4729x over previous
#include <cuda_runtime.h>
#include <cuda.h>
#include <cstdint>

// ---------------- problem constants ----------------
#define N_ROWS  16384
#define D_IN    64
#define D_OUT   32
#define N_PAD   40               // 32 nom | 32:den | 33:alpha | 34..39 zero (5 n8-tiles)
#define TM      128              // rows per CTA
#define TK      32               // K per pipeline stage
#define STAGES  8
#define K_ITERS (N_ROWS / TK)    // 512

#define B_LANE_STRIDE 44                         // floats per lane row (odd # of 16B units)
#define STAGE_A_BYTES (TM * TK * 4)              // 16384
#define STAGE_B_BYTES (32 * B_LANE_STRIDE * 4)   // 5632
#define STAGE_BYTES   22528                      // A + B padded to 1024 multiple
#define SMEM_DYN      (STAGES * STAGE_BYTES + 1024)

#define NWARPS_C 4               // consumer warps, M=32 each (2 m16 row-blocks)
#define NTHREADS (32 * (NWARPS_C + 1))

// B operand, fragment-packed: [K_ITERS][32 lanes][44 floats], tf32-rounded.
// lane row j index: j = ((ks*5)+nt)*2 + h  ->  B[k = ks*8+h*4+(lane&3)][n = nt*8+(lane>>2)]
__device__ float g_Bpk[K_ITERS * 32 * B_LANE_STRIDE];

// ---------------- device helpers ----------------
__device__ __forceinline__ uint32_t smem_u32(const void* p) {
    uint32_t a;
    asm("{ .reg .u64 t; cvta.to.shared.u64 t, %1; cvt.u32.u64 %0, t; }" : "=r"(a) : "l"(p));
    return a;
}
__device__ __forceinline__ float warp_sum(float v) {
    #pragma unroll
    for (int m = 16; m > 0; m >>= 1) v += __shfl_xor_sync(0xffffffffu, v, m);
    return v;
}
__device__ __forceinline__ float artanh_clip(float x) {
    x = fminf(fmaxf(x, -1.0f + 1e-7f), 1.0f - 1e-7f);
    return atanhf(x);
}
__device__ __forceinline__ float tf32_round(float x) {
    uint32_t u;
    asm("cvt.rna.tf32.f32 %0, %1;" : "=r"(u) : "f"(x));
    return __uint_as_float(u);
}
__device__ __forceinline__ uint32_t tf32_bits(float x) {
    uint32_t u;
    asm("cvt.rna.tf32.f32 %0, %1;" : "=r"(u) : "f"(x));
    return u;
}
__device__ __forceinline__ void mbar_init(uint32_t mbar, uint32_t cnt) {
    asm volatile("mbarrier.init.shared.b64 [%0], %1;" :: "r"(mbar), "r"(cnt) : "memory");
}
__device__ __forceinline__ void mbar_expect_tx(uint32_t mbar, uint32_t bytes) {
    asm volatile("mbarrier.arrive.expect_tx.shared.b64 _, [%0], %1;" :: "r"(mbar), "r"(bytes) : "memory");
}
__device__ __forceinline__ void mbar_arrive(uint32_t mbar) {
    asm volatile("mbarrier.arrive.shared.b64 _, [%0];" :: "r"(mbar) : "memory");
}
__device__ __forceinline__ void mbar_wait(uint32_t mbar, uint32_t parity) {
    asm volatile(
        "{\n\t.reg .pred P;\n\t"
        "WL_%=:\n\t"
        "mbarrier.try_wait.parity.shared.b64 P, [%0], %1;\n\t"
        "@!P bra WL_%=;\n\t"
        "}" :: "r"(mbar), "r"(parity) : "memory");
}
__device__ __forceinline__ void tma_load_2d(uint32_t smem_dst, const void* tmap,
                                            int32_t cx, int32_t cy, uint32_t mbar) {
    asm volatile(
        "cp.async.bulk.tensor.2d.shared::cta.global.tile.mbarrier::complete_tx::bytes "
        "[%0], [%1, {%2, %3}], [%4];"
        :: "r"(smem_dst), "l"(tmap), "r"(cx), "r"(cy), "r"(mbar) : "memory");
}
__device__ __forceinline__ void bulk_load(uint32_t smem_dst, const void* gsrc,
                                          uint32_t bytes, uint32_t mbar) {
    asm volatile(
        "cp.async.bulk.shared::cta.global.mbarrier::complete_tx::bytes [%0], [%1], %2, [%3];"
        :: "r"(smem_dst), "l"(gsrc), "r"(bytes), "r"(mbar) : "memory");
}
__device__ __forceinline__ float lds32(uint32_t a) {
    float v;
    asm volatile("ld.shared.f32 %0, [%1];" : "=f"(v) : "r"(a));
    return v;
}
__device__ __forceinline__ void lds128(uint32_t a, uint32_t r[4]) {
    asm volatile("ld.shared.v4.u32 {%0,%1,%2,%3}, [%4];"
                 : "=r"(r[0]), "=r"(r[1]), "=r"(r[2]), "=r"(r[3]) : "r"(a));
}
__device__ __forceinline__ void mma_tf32(float c[4], uint32_t a0, uint32_t a1, uint32_t a2, uint32_t a3,
                                         uint32_t b0, uint32_t b1) {
    asm volatile(
        "mma.sync.aligned.m16n8k8.row.col.f32.tf32.tf32.f32 "
        "{%0,%1,%2,%3}, {%4,%5,%6,%7}, {%8,%9}, {%0,%1,%2,%3};"
        : "+f"(c[0]), "+f"(c[1]), "+f"(c[2]), "+f"(c[3])
        : "r"(a0), "r"(a1), "r"(a2), "r"(a3), "r"(b0), "r"(b1));
}

// ---------------- kernel 1: build fragment-packed B ----------------
__global__ __launch_bounds__(1024) void prep_kernel(const float* __restrict__ X,
                                                    const float* __restrict__ W) {
    __shared__ float Ws[D_IN * D_OUT];
    const int tid = threadIdx.x;
    for (int t = tid; t < D_IN * D_OUT; t += 1024) Ws[t] = W[t];
    __syncthreads();

    const int w = tid >> 5, lane = tid & 31;
    const int i = blockIdx.x * 32 + w;           // global row (= K index of B)

    const float x0 = X[i * D_IN + lane];
    const float x1 = X[i * D_IN + 32 + lane];
    const float xn = fmaxf(sqrtf(warp_sum(x0 * x0 + x1 * x1)), 1e-15f);

    float mx = 0.0f;
    #pragma unroll
    for (int k = 0; k < 32; ++k) mx = fmaf(__shfl_sync(0xffffffffu, x0, k), Ws[k * 32 + lane], mx);
    #pragma unroll
    for (int k = 0; k < 32; ++k) mx = fmaf(__shfl_sync(0xffffffffu, x1, k), Ws[(k + 32) * 32 + lane], mx);

    const float mxn = fmaxf(sqrtf(warp_sum(mx * mx)), 1e-15f);
    const float t   = tanhf((mxn / xn) * artanh_clip(xn));
    const float xw  = t * (mx / mxn);
    const float x2  = warp_sum(xw * xw);
    const float gamma = 2.0f / fmaxf(1.0f - x2, 1e-15f);

    // scatter into fragment-packed layout
    const int ks = (i & 31) >> 3;
    const int h  = (i >> 2) & 1;
    const int il = i & 3;
    const int kiter = i >> 5;
    float* base = g_Bpk + (size_t)kiter * (32 * B_LANE_STRIDE);

    {   // n = lane (0..31): value xw*gamma
        const int n = lane;
        const int tl = il | ((n & 7) << 2);
        const int j  = ((ks * 5) + (n >> 3)) * 2 + h;
        base[tl * B_LANE_STRIDE + j] = tf32_round(xw * gamma);
    }
    if (lane < 2) {  // n = 32 (gamma-1), n = 33 (1.0); n=34..39 stay zero
        const int n = 32 + lane;
        const float e = (lane == 0) ? (gamma - 1.0f) : 1.0f;
        const int tl = il | ((n & 7) << 2);
        const int j  = ((ks * 5) + 4) * 2 + h;
        base[tl * B_LANE_STRIDE + j] = tf32_round(e);
    }
}

// ---------------- kernel 2: A @ Y via TMA + mma.sync.tf32 ----------------
__global__ __launch_bounds__(NTHREADS, 1) void gemm_kernel(
    const __grid_constant__ CUtensorMap tmA,
    const float* __restrict__ Bpk,
    float* __restrict__ out)
{
    extern __shared__ uint8_t smem_dyn[];
    __shared__ __align__(8) uint64_t full_b[STAGES];
    __shared__ __align__(8) uint64_t empty_b[STAGES];

    const int tid  = threadIdx.x;
    const int wid  = tid >> 5;
    const int lane = tid & 31;

    const uint32_t dyn_base = (smem_u32(smem_dyn) + 1023u) & ~1023u;
    const uint32_t full0  = smem_u32(&full_b[0]);
    const uint32_t empty0 = smem_u32(&empty_b[0]);

    if (tid == 0) {
        for (int s = 0; s < STAGES; ++s) {
            mbar_init(full0 + 8u * s, 1);
            mbar_init(empty0 + 8u * s, NWARPS_C);
        }
    }
    __syncthreads();

    const int row_base = blockIdx.x * TM;

    if (wid == NWARPS_C) {
        // -------- producer --------
        if (lane == 0) {
            uint32_t phase = 1;
            for (int it = 0; it < K_ITERS; ++it) {
                const int s = it & (STAGES - 1);
                mbar_wait(empty0 + 8u * s, phase);
                const uint32_t fb = full0 + 8u * s;
                mbar_expect_tx(fb, STAGE_A_BYTES + STAGE_B_BYTES);
                const uint32_t a_dst = dyn_base + s * STAGE_BYTES;
                tma_load_2d(a_dst, &tmA, it * TK, row_base, fb);            // A box [32 x 128] SW128
                bulk_load(a_dst + STAGE_A_BYTES,
                          Bpk + (size_t)it * (32 * B_LANE_STRIDE),
                          STAGE_B_BYTES, fb);                               // packed B, 5632B
                if (s == STAGES - 1) phase ^= 1;
            }
        }
        return;
    }

    // -------- consumers: 4 warps, warp owns rows [wid*32, wid*32+32) --------
    float acc[2][5][4];
    #pragma unroll
    for (int rb = 0; rb < 2; ++rb)
        #pragma unroll
        for (int nt = 0; nt < 5; ++nt)
            #pragma unroll
            for (int q = 0; q < 4; ++q) acc[rb][nt][q] = 0.0f;

    const uint32_t lane2 = lane & 3u, lane4 = lane >> 2;
    const uint32_t sw    = lane4 << 4;                    // SW128 XOR term (row&7 == lane4)
    const uint32_t aoff0 = (uint32_t)(wid * 32 + lane4) * 128u;
    const uint32_t boff  = STAGE_A_BYTES + lane * (B_LANE_STRIDE * 4u);

    uint32_t phase = 0;
    for (int it = 0; it < K_ITERS; ++it) {
        const int s = it & (STAGES - 1);
        mbar_wait(full0 + 8u * s, phase);
        const uint32_t Abase = dyn_base + (uint32_t)s * STAGE_BYTES;

        // ---- B: 10x LDS.128 -> 40 tf32 regs ----
        uint32_t br[40];
        {
            const uint32_t bb = Abase + boff;
            #pragma unroll
            for (int q = 0; q < 10; ++q) lds128(bb + 16u * q, &br[4 * q]);
        }
        // ---- A: 32 scalar LDS -> staged, then cvt ----
        float afl[2][4][4];
        #pragma unroll
        for (int rb = 0; rb < 2; ++rb) {
            const uint32_t r0 = Abase + aoff0 + (uint32_t)rb * (16u * 128u);
            #pragma unroll
            for (int ks = 0; ks < 4; ++ks) {
                const uint32_t c0 = (uint32_t)ks * 32u + lane2 * 4u;
                afl[rb][ks][0] = lds32(r0 +          (c0 ^ sw));
                afl[rb][ks][1] = lds32(r0 + 1024u +  (c0 ^ sw));
                afl[rb][ks][2] = lds32(r0 +         ((c0 + 16u) ^ sw));
                afl[rb][ks][3] = lds32(r0 + 1024u + ((c0 + 16u) ^ sw));
            }
        }
        uint32_t au[2][4][4];
        #pragma unroll
        for (int rb = 0; rb < 2; ++rb)
            #pragma unroll
            for (int ks = 0; ks < 4; ++ks)
                #pragma unroll
                for (int q = 0; q < 4; ++q) au[rb][ks][q] = tf32_bits(afl[rb][ks][q]);

        if (lane == 0) mbar_arrive(empty0 + 8u * s);   // regs hold everything; TMA rewrite is >=300cyc away

        #pragma unroll
        for (int ks = 0; ks < 4; ++ks)
            #pragma unroll
            for (int rb = 0; rb < 2; ++rb)
                #pragma unroll
                for (int nt = 0; nt < 5; ++nt)
                    mma_tf32(acc[rb][nt],
                             au[rb][ks][0], au[rb][ks][1], au[rb][ks][2], au[rb][ks][3],
                             br[(ks * 5 + nt) * 2], br[(ks * 5 + nt) * 2 + 1]);

        if (s == STAGES - 1) phase ^= 1;
    }

    // -------- epilogue: hyperbolic chain per (row-block, row-half) --------
    #pragma unroll
    for (int rb = 0; rb < 2; ++rb)
    #pragma unroll
    for (int h = 0; h < 2; ++h) {
        float v[8];
        #pragma unroll
        for (int nt = 0; nt < 4; ++nt) {
            v[2 * nt]     = acc[rb][nt][2 * h];
            v[2 * nt + 1] = acc[rb][nt][2 * h + 1];
        }
        float den   = __shfl_sync(0xffffffffu, acc[rb][4][2 * h],     lane & ~3);
        float alpha = __shfl_sync(0xffffffffu, acc[rb][4][2 * h + 1], lane & ~3);

        const float sgn = (den >= 0.0f) ? 1.0f : -1.0f;
        den = sgn * fmaxf(fabsf(den), 1e-10f);
        const float inv = 1.0f / den;

        float vn2 = 0.0f;
        #pragma unroll
        for (int c = 0; c < 8; ++c) { v[c] *= inv; vn2 += v[c] * v[c]; }
        vn2 += __shfl_xor_sync(0xffffffffu, vn2, 1);
        vn2 += __shfl_xor_sync(0xffffffffu, vn2, 2);

        const float vn = fmaxf(sqrtf(vn2), 1e-15f);
        const float t1 = tanhf(0.5f * artanh_clip(vn));
        const float rn = fmaxf(t1, 1e-15f);
        const float t2 = tanhf(alpha * artanh_clip(rn));
        const float xs = (t1 / vn) * (t2 / rn);
        const float xn = fmaxf(xs * vn, 1e-15f);
        const float k3 = artanh_clip(xn) / xn;
        const float us = xs * k3;

        float un2 = 0.0f;
        float u[8];
        #pragma unroll
        for (int c = 0; c < 8; ++c) { u[c] = fmaxf(v[c] * us, 0.0f); un2 += u[c] * u[c]; }
        un2 += __shfl_xor_sync(0xffffffffu, un2, 1);
        un2 += __shfl_xor_sync(0xffffffffu, un2, 2);

        const float un = fmaxf(sqrtf(un2), 1e-15f);
        const float k4 = tanhf(un) / un;

        const int row = row_base + wid * 32 + rb * 16 + h * 8 + (lane >> 2);
        float* op = out + (size_t)row * D_OUT + 2 * (lane & 3);
        #pragma unroll
        for (int nt = 0; nt < 4; ++nt)
            *reinterpret_cast<float2*>(op + nt * 8) =
                make_float2(u[2 * nt] * k4, u[2 * nt + 1] * k4);
    }
}

// ---------------- host ----------------
typedef CUresult (CUDAAPI *PFN_cuTensorMapEncodeTiled_t)(
    CUtensorMap*, CUtensorMapDataType, cuuint32_t, void*,
    const cuuint64_t*, const cuuint64_t*, const cuuint32_t*, const cuuint32_t*,
    CUtensorMapInterleave, CUtensorMapSwizzle, CUtensorMapL2promotion, CUtensorMapFloatOOBfill);

extern "C" void kernel_launch(void* const* d_in, const int* in_sizes, int n_in,
                              void* d_out, int out_size) {
    const float* X = nullptr; const float* A = nullptr; const float* W = nullptr;
    for (int i = 0; i < n_in; ++i) {
        if (in_sizes[i] == N_ROWS * D_IN)     X = (const float*)d_in[i];
        else if (in_sizes[i] == D_IN * D_OUT) W = (const float*)d_in[i];
        else                                  A = (const float*)d_in[i];   // 16384^2
    }
    float* out = (float*)d_out;

    void* b_ptr = nullptr;
    cudaGetSymbolAddress(&b_ptr, g_Bpk);

    PFN_cuTensorMapEncodeTiled_t encode = nullptr;
    cudaDriverEntryPointQueryResult qr;
    cudaGetDriverEntryPointByVersion("cuTensorMapEncodeTiled", (void**)&encode,
                                     12000, cudaEnableDefault, &qr);

    CUtensorMap tmA;
    {   // A: [16384 x 16384] fp32, box [K=32, M=128], SW128
        cuuint64_t dims[2]    = {N_ROWS, N_ROWS};
        cuuint64_t strides[1] = {(cuuint64_t)N_ROWS * 4};
        cuuint32_t box[2]     = {TK, TM};
        cuuint32_t estr[2]    = {1, 1};
        encode(&tmA, CU_TENSOR_MAP_DATA_TYPE_FLOAT32, 2, (void*)A,
               dims, strides, box, estr,
               CU_TENSOR_MAP_INTERLEAVE_NONE, CU_TENSOR_MAP_SWIZZLE_128B,
               CU_TENSOR_MAP_L2_PROMOTION_L2_128B, CU_TENSOR_MAP_FLOAT_OOB_FILL_NONE);
    }

    prep_kernel<<<N_ROWS / 32, 1024>>>(X, W);

    cudaFuncSetAttribute(gemm_kernel, cudaFuncAttributeMaxDynamicSharedMemorySize, SMEM_DYN);
    gemm_kernel<<<N_ROWS / TM, NTHREADS, SMEM_DYN>>>(tmA, (const float*)b_ptr, out);
}

// round 7
// speedup vs baseline: 1.5432x; 1.0478x over previous
#include <cuda_runtime.h>
#include <cuda.h>
#include <cstdint>

// ---------------- problem constants ----------------
#define N_ROWS  16384
#define D_IN    64
#define D_OUT   32
#define N_PAD   40               // 32 nom | 32:den | 33:alpha | 34..39 zero (5 n8-tiles)
#define TM      64               // rows per CTA (2 CTAs/SM, grid 256 -> one wave on 148 SMs)
#define TK      32               // K per pipeline stage
#define STAGES  6
#define K_ITERS (N_ROWS / TK)    // 512

#define B_LANE_STRIDE 44                         // floats per lane row (odd # of 16B units)
#define STAGE_A_BYTES (TM * TK * 4)              // 8192
#define STAGE_B_BYTES (32 * B_LANE_STRIDE * 4)   // 5632
#define STAGE_BYTES   14336                      // A + B padded to 1024 multiple
#define SMEM_DYN      (STAGES * STAGE_BYTES + 1024)   // 87040

#define NWARPS_C 4               // consumer warps, M=16 each
#define NTHREADS (32 * (NWARPS_C + 1))
#define GRID     (N_ROWS / TM)   // 256

// B operand, fragment-packed: [K_ITERS][32 lanes][44 floats], tf32-rounded.
// lane row j index: j = ((ks*5)+nt)*2 + h  ->  B[k = ks*8+h*4+(lane&3)][n = nt*8+(lane>>2)]
__device__ float g_Bpk[K_ITERS * 32 * B_LANE_STRIDE];

// ---------------- device helpers ----------------
__device__ __forceinline__ uint32_t smem_u32(const void* p) {
    uint32_t a;
    asm("{ .reg .u64 t; cvta.to.shared.u64 t, %1; cvt.u32.u64 %0, t; }" : "=r"(a) : "l"(p));
    return a;
}
__device__ __forceinline__ float warp_sum(float v) {
    #pragma unroll
    for (int m = 16; m > 0; m >>= 1) v += __shfl_xor_sync(0xffffffffu, v, m);
    return v;
}
__device__ __forceinline__ float artanh_clip(float x) {
    x = fminf(fmaxf(x, -1.0f + 1e-7f), 1.0f - 1e-7f);
    return atanhf(x);
}
__device__ __forceinline__ float tf32_round(float x) {
    uint32_t u;
    asm("cvt.rna.tf32.f32 %0, %1;" : "=r"(u) : "f"(x));
    return __uint_as_float(u);
}
__device__ __forceinline__ uint32_t tf32_bits(float x) {
    uint32_t u;
    asm("cvt.rna.tf32.f32 %0, %1;" : "=r"(u) : "f"(x));
    return u;
}
__device__ __forceinline__ void mbar_init(uint32_t mbar, uint32_t cnt) {
    asm volatile("mbarrier.init.shared.b64 [%0], %1;" :: "r"(mbar), "r"(cnt) : "memory");
}
__device__ __forceinline__ void mbar_expect_tx(uint32_t mbar, uint32_t bytes) {
    asm volatile("mbarrier.arrive.expect_tx.shared.b64 _, [%0], %1;" :: "r"(mbar), "r"(bytes) : "memory");
}
__device__ __forceinline__ void mbar_arrive(uint32_t mbar) {
    asm volatile("mbarrier.arrive.shared.b64 _, [%0];" :: "r"(mbar) : "memory");
}
__device__ __forceinline__ void mbar_wait(uint32_t mbar, uint32_t parity) {
    asm volatile(
        "{\n\t.reg .pred P;\n\t"
        "WL_%=:\n\t"
        "mbarrier.try_wait.parity.shared.b64 P, [%0], %1;\n\t"
        "@!P bra WL_%=;\n\t"
        "}" :: "r"(mbar), "r"(parity) : "memory");
}
__device__ __forceinline__ void tma_load_2d(uint32_t smem_dst, const void* tmap,
                                            int32_t cx, int32_t cy, uint32_t mbar) {
    asm volatile(
        "cp.async.bulk.tensor.2d.shared::cta.global.tile.mbarrier::complete_tx::bytes "
        "[%0], [%1, {%2, %3}], [%4];"
        :: "r"(smem_dst), "l"(tmap), "r"(cx), "r"(cy), "r"(mbar) : "memory");
}
__device__ __forceinline__ void bulk_load(uint32_t smem_dst, const void* gsrc,
                                          uint32_t bytes, uint32_t mbar) {
    asm volatile(
        "cp.async.bulk.shared::cta.global.mbarrier::complete_tx::bytes [%0], [%1], %2, [%3];"
        :: "r"(smem_dst), "l"(gsrc), "r"(bytes), "r"(mbar) : "memory");
}
__device__ __forceinline__ float lds32(uint32_t a) {
    float v;
    asm volatile("ld.shared.f32 %0, [%1];" : "=f"(v) : "r"(a));
    return v;
}
__device__ __forceinline__ void lds128(uint32_t a, uint32_t r[4]) {
    asm volatile("ld.shared.v4.u32 {%0,%1,%2,%3}, [%4];"
                 : "=r"(r[0]), "=r"(r[1]), "=r"(r[2]), "=r"(r[3]) : "r"(a));
}
__device__ __forceinline__ void mma_tf32(float c[4], uint32_t a0, uint32_t a1, uint32_t a2, uint32_t a3,
                                         uint32_t b0, uint32_t b1) {
    asm volatile(
        "mma.sync.aligned.m16n8k8.row.col.f32.tf32.tf32.f32 "
        "{%0,%1,%2,%3}, {%4,%5,%6,%7}, {%8,%9}, {%0,%1,%2,%3};"
        : "+f"(c[0]), "+f"(c[1]), "+f"(c[2]), "+f"(c[3])
        : "r"(a0), "r"(a1), "r"(a2), "r"(a3), "r"(b0), "r"(b1));
}

// ---------------- kernel 1: build fragment-packed B ----------------
__global__ __launch_bounds__(1024) void prep_kernel(const float* __restrict__ X,
                                                    const float* __restrict__ W) {
    __shared__ float Ws[D_IN * D_OUT];
    const int tid = threadIdx.x;
    for (int t = tid; t < D_IN * D_OUT; t += 1024) Ws[t] = W[t];
    __syncthreads();

    const int w = tid >> 5, lane = tid & 31;
    const int i = blockIdx.x * 32 + w;           // global row (= K index of B)

    const float x0 = X[i * D_IN + lane];
    const float x1 = X[i * D_IN + 32 + lane];
    const float xn = fmaxf(sqrtf(warp_sum(x0 * x0 + x1 * x1)), 1e-15f);

    float mx = 0.0f;
    #pragma unroll
    for (int k = 0; k < 32; ++k) mx = fmaf(__shfl_sync(0xffffffffu, x0, k), Ws[k * 32 + lane], mx);
    #pragma unroll
    for (int k = 0; k < 32; ++k) mx = fmaf(__shfl_sync(0xffffffffu, x1, k), Ws[(k + 32) * 32 + lane], mx);

    const float mxn = fmaxf(sqrtf(warp_sum(mx * mx)), 1e-15f);
    const float t   = tanhf((mxn / xn) * artanh_clip(xn));
    const float xw  = t * (mx / mxn);
    const float x2  = warp_sum(xw * xw);
    const float gamma = 2.0f / fmaxf(1.0f - x2, 1e-15f);

    // scatter into fragment-packed layout
    const int ks = (i & 31) >> 3;
    const int h  = (i >> 2) & 1;
    const int il = i & 3;
    const int kiter = i >> 5;
    float* base = g_Bpk + (size_t)kiter * (32 * B_LANE_STRIDE);

    {   // n = lane (0..31): value xw*gamma
        const int n = lane;
        const int tl = il | ((n & 7) << 2);
        const int j  = ((ks * 5) + (n >> 3)) * 2 + h;
        base[tl * B_LANE_STRIDE + j] = tf32_round(xw * gamma);
    }
    if (lane < 2) {  // n = 32 (gamma-1), n = 33 (1.0); n=34..39 stay zero
        const int n = 32 + lane;
        const float e = (lane == 0) ? (gamma - 1.0f) : 1.0f;
        const int tl = il | ((n & 7) << 2);
        const int j  = ((ks * 5) + 4) * 2 + h;
        base[tl * B_LANE_STRIDE + j] = tf32_round(e);
    }
}

// ---------------- kernel 2: A @ Y via TMA + mma.sync.tf32 ----------------
__global__ __launch_bounds__(NTHREADS, 2) void gemm_kernel(
    const __grid_constant__ CUtensorMap tmA,
    const float* __restrict__ Bpk,
    float* __restrict__ out)
{
    extern __shared__ uint8_t smem_dyn[];
    __shared__ __align__(8) uint64_t full_b[STAGES];
    __shared__ __align__(8) uint64_t empty_b[STAGES];

    const int tid  = threadIdx.x;
    const int wid  = tid >> 5;
    const int lane = tid & 31;

    const uint32_t dyn_base = (smem_u32(smem_dyn) + 1023u) & ~1023u;
    const uint32_t full0  = smem_u32(&full_b[0]);
    const uint32_t empty0 = smem_u32(&empty_b[0]);

    if (tid == 0) {
        for (int s = 0; s < STAGES; ++s) {
            mbar_init(full0 + 8u * s, 1);
            mbar_init(empty0 + 8u * s, NWARPS_C);
        }
    }
    __syncthreads();

    const int row_base = blockIdx.x * TM;

    if (wid == NWARPS_C) {
        // -------- producer --------
        if (lane == 0) {
            uint32_t phase = 1;   // fresh-barrier trick: first empty-wait passes
            int s = 0;
            for (int it = 0; it < K_ITERS; ++it) {
                mbar_wait(empty0 + 8u * s, phase);
                const uint32_t fb = full0 + 8u * s;
                mbar_expect_tx(fb, STAGE_A_BYTES + STAGE_B_BYTES);
                const uint32_t a_dst = dyn_base + (uint32_t)s * STAGE_BYTES;
                tma_load_2d(a_dst, &tmA, it * TK, row_base, fb);            // A box [32 x 64] SW128
                bulk_load(a_dst + STAGE_A_BYTES,
                          Bpk + (size_t)it * (32 * B_LANE_STRIDE),
                          STAGE_B_BYTES, fb);                               // packed B, 5632B
                if (++s == STAGES) { s = 0; phase ^= 1; }
            }
        }
        return;
    }

    // -------- consumers: 4 warps, warp owns rows [wid*16, wid*16+16) --------
    float acc[5][4];
    #pragma unroll
    for (int nt = 0; nt < 5; ++nt)
        #pragma unroll
        for (int q = 0; q < 4; ++q) acc[nt][q] = 0.0f;

    const uint32_t lane2 = lane & 3u, lane4 = lane >> 2;
    const uint32_t sw    = lane4 << 4;                    // SW128 XOR term (row&7 == lane4)
    const uint32_t aoff0 = (uint32_t)(wid * 16 + lane4) * 128u;
    const uint32_t boff  = STAGE_A_BYTES + lane * (B_LANE_STRIDE * 4u);

    uint32_t phase = 0;
    int s = 0;
    for (int it = 0; it < K_ITERS; ++it) {
        mbar_wait(full0 + 8u * s, phase);
        const uint32_t Abase = dyn_base + (uint32_t)s * STAGE_BYTES;

        // ---- B: 10x LDS.128 -> 40 tf32 regs ----
        uint32_t br[40];
        {
            const uint32_t bb = Abase + boff;
            #pragma unroll
            for (int q = 0; q < 10; ++q) lds128(bb + 16u * q, &br[4 * q]);
        }
        // ---- A: 16 scalar LDS -> staged, then cvt ----
        float afl[4][4];
        {
            const uint32_t r0 = Abase + aoff0;
            #pragma unroll
            for (int ks = 0; ks < 4; ++ks) {
                const uint32_t c0 = (uint32_t)ks * 32u + lane2 * 4u;
                afl[ks][0] = lds32(r0 +          (c0 ^ sw));
                afl[ks][1] = lds32(r0 + 1024u +  (c0 ^ sw));
                afl[ks][2] = lds32(r0 +         ((c0 + 16u) ^ sw));
                afl[ks][3] = lds32(r0 + 1024u + ((c0 + 16u) ^ sw));
            }
        }
        uint32_t au[4][4];
        #pragma unroll
        for (int ks = 0; ks < 4; ++ks)
            #pragma unroll
            for (int q = 0; q < 4; ++q) au[ks][q] = tf32_bits(afl[ks][q]);

        if (lane == 0) mbar_arrive(empty0 + 8u * s);   // regs hold everything

        #pragma unroll
        for (int ks = 0; ks < 4; ++ks)
            #pragma unroll
            for (int nt = 0; nt < 5; ++nt)
                mma_tf32(acc[nt],
                         au[ks][0], au[ks][1], au[ks][2], au[ks][3],
                         br[(ks * 5 + nt) * 2], br[(ks * 5 + nt) * 2 + 1]);

        if (++s == STAGES) { s = 0; phase ^= 1; }
    }

    // -------- epilogue: hyperbolic chain per row-half --------
    #pragma unroll
    for (int h = 0; h < 2; ++h) {
        float v[8];
        #pragma unroll
        for (int nt = 0; nt < 4; ++nt) {
            v[2 * nt]     = acc[nt][2 * h];
            v[2 * nt + 1] = acc[nt][2 * h + 1];
        }
        float den   = __shfl_sync(0xffffffffu, acc[4][2 * h],     lane & ~3);
        float alpha = __shfl_sync(0xffffffffu, acc[4][2 * h + 1], lane & ~3);

        const float sgn = (den >= 0.0f) ? 1.0f : -1.0f;
        den = sgn * fmaxf(fabsf(den), 1e-10f);
        const float inv = 1.0f / den;

        float vn2 = 0.0f;
        #pragma unroll
        for (int c = 0; c < 8; ++c) { v[c] *= inv; vn2 += v[c] * v[c]; }
        vn2 += __shfl_xor_sync(0xffffffffu, vn2, 1);
        vn2 += __shfl_xor_sync(0xffffffffu, vn2, 2);

        const float vn = fmaxf(sqrtf(vn2), 1e-15f);
        const float t1 = tanhf(0.5f * artanh_clip(vn));
        const float rn = fmaxf(t1, 1e-15f);
        const float t2 = tanhf(alpha * artanh_clip(rn));
        const float xs = (t1 / vn) * (t2 / rn);
        const float xn = fmaxf(xs * vn, 1e-15f);
        const float k3 = artanh_clip(xn) / xn;
        const float us = xs * k3;

        float un2 = 0.0f;
        float u[8];
        #pragma unroll
        for (int c = 0; c < 8; ++c) { u[c] = fmaxf(v[c] * us, 0.0f); un2 += u[c] * u[c]; }
        un2 += __shfl_xor_sync(0xffffffffu, un2, 1);
        un2 += __shfl_xor_sync(0xffffffffu, un2, 2);

        const float un = fmaxf(sqrtf(un2), 1e-15f);
        const float k4 = tanhf(un) / un;

        const int row = row_base + wid * 16 + h * 8 + (lane >> 2);
        float* op = out + (size_t)row * D_OUT + 2 * (lane & 3);
        #pragma unroll
        for (int nt = 0; nt < 4; ++nt)
            *reinterpret_cast<float2*>(op + nt * 8) =
                make_float2(u[2 * nt] * k4, u[2 * nt + 1] * k4);
    }
}

// ---------------- host ----------------
typedef CUresult (CUDAAPI *PFN_cuTensorMapEncodeTiled_t)(
    CUtensorMap*, CUtensorMapDataType, cuuint32_t, void*,
    const cuuint64_t*, const cuuint64_t*, const cuuint32_t*, const cuuint32_t*,
    CUtensorMapInterleave, CUtensorMapSwizzle, CUtensorMapL2promotion, CUtensorMapFloatOOBfill);

extern "C" void kernel_launch(void* const* d_in, const int* in_sizes, int n_in,
                              void* d_out, int out_size) {
    const float* X = nullptr; const float* A = nullptr; const float* W = nullptr;
    for (int i = 0; i < n_in; ++i) {
        if (in_sizes[i] == N_ROWS * D_IN)     X = (const float*)d_in[i];
        else if (in_sizes[i] == D_IN * D_OUT) W = (const float*)d_in[i];
        else                                  A = (const float*)d_in[i];   // 16384^2
    }
    float* out = (float*)d_out;

    void* b_ptr = nullptr;
    cudaGetSymbolAddress(&b_ptr, g_Bpk);

    PFN_cuTensorMapEncodeTiled_t encode = nullptr;
    cudaDriverEntryPointQueryResult qr;
    cudaGetDriverEntryPointByVersion("cuTensorMapEncodeTiled", (void**)&encode,
                                     12000, cudaEnableDefault, &qr);

    CUtensorMap tmA;
    {   // A: [16384 x 16384] fp32, box [K=32, M=64], SW128
        cuuint64_t dims[2]    = {N_ROWS, N_ROWS};
        cuuint64_t strides[1] = {(cuuint64_t)N_ROWS * 4};
        cuuint32_t box[2]     = {TK, TM};
        cuuint32_t estr[2]    = {1, 1};
        encode(&tmA, CU_TENSOR_MAP_DATA_TYPE_FLOAT32, 2, (void*)A,
               dims, strides, box, estr,
               CU_TENSOR_MAP_INTERLEAVE_NONE, CU_TENSOR_MAP_SWIZZLE_128B,
               CU_TENSOR_MAP_L2_PROMOTION_L2_128B, CU_TENSOR_MAP_FLOAT_OOB_FILL_NONE);
    }

    prep_kernel<<<N_ROWS / 32, 1024>>>(X, W);

    cudaFuncSetAttribute(gemm_kernel, cudaFuncAttributeMaxDynamicSharedMemorySize, SMEM_DYN);
    gemm_kernel<<<GRID, NTHREADS, SMEM_DYN>>>(tmA, (const float*)b_ptr, out);
}